// round 14
// baseline (speedup 1.0000x reference)
#include <cuda_runtime.h>
#include <cuda_fp16.h>
#include <math.h>

#define NN 100000
#define NP 100352         // NN padded to 2048 multiple (scan tiles)
#define EE 1600000
#define FF 16
#define HH 128
#define NSB 49            // scan blocks: ceil(NP/2048)

// ---------------- scratch (device globals; no allocation allowed) ----------
__device__ __align__(16) __half2 g_Ah[(size_t)NN * 64];  // h @ W_h (fp16, 256B/row)
__device__ __align__(16) float g_B[(size_t)NN * HH];     // feat @ W_f + b_nm
__device__ __align__(16) __half g_W1h[HH * HH];          // W_out1 in fp16
__device__ float g_as[NN];
__device__ float g_ad[NN];
__device__ __align__(16) int g_deg[NP];
__device__ __align__(16) int g_off[NP];
__device__ __align__(16) int g_cur[NP];
__device__ volatile int g_sstat[NSB];            // 0=invalid 1=agg 2=prefix
__device__ volatile int g_sagg[NSB];
__device__ volatile int g_spref[NSB];
__device__ int   g_srcv[EE];                    // CSR-ordered src node
__device__ __align__(8) float2 g_lb[EE];        // CSR-ordered (ee, ee*bit)
__device__ __align__(16) float g_W2h[64 * HH];
__device__ __align__(16) float g_bA[HH];
__device__ float g_c;

__device__ __forceinline__ float lrelu(float x, float s) { return fmaxf(x, s * x); }

// packed fp32x2 helpers (Blackwell FFMA2: 2x fp32 FMA issue rate)
__device__ __forceinline__ unsigned long long pk2(float x, float y) {
    unsigned long long r; asm("mov.b64 %0,{%1,%2};" : "=l"(r) : "f"(x), "f"(y)); return r;
}
__device__ __forceinline__ float2 upk2(unsigned long long v) {
    float2 r; asm("mov.b64 {%0,%1},%2;" : "=f"(r.x), "=f"(r.y) : "l"(v)); return r;
}
__device__ __forceinline__ unsigned long long fma2(unsigned long long a,
                                                   unsigned long long b,
                                                   unsigned long long c) {
    unsigned long long d;
    asm("fma.rn.f32x2 %0,%1,%2,%3;" : "=l"(d) : "l"(a), "l"(b), "l"(c));
    return d;
}

// ---------------- f0: zero deg/status + W2h fold + bias + c + W1->fp16 -----
__global__ __launch_bounds__(256) void f0_init(
    const float* __restrict__ W_self2, const float* __restrict__ b_self2,
    const float* __restrict__ W_nm, const float* __restrict__ attn,
    const float* __restrict__ W_out1) {
    int bid = blockIdx.x, tid = threadIdx.x;
    if (bid < 392) {                       // zero g_deg (incl. padding) + statuses
        int i = bid * 256 + tid;
        if (i < NP) g_deg[i] = 0;
        if (bid == 0 && tid < NSB) g_sstat[tid] = 0;
    } else if (bid < 424) {                // 32 blocks: 2 rows of W2h each
        int i = (bid - 392) * 2 + (tid >> 7);
        int j = tid & 127;
        float acc = 0.f;
        for (int k = 0; k < 128; ++k)
            acc = fmaf(W_self2[i * 128 + k], W_nm[k * 128 + j], acc);
        g_W2h[i * 128 + j] = acc;
    } else if (bid == 424) {               // bias fold + scalar c
        __shared__ float red[128];
        if (tid < 128) {
            float acc = 0.f;
            for (int k = 0; k < 128; ++k)
                acc = fmaf(b_self2[k], W_nm[k * 128 + tid], acc);
            g_bA[tid] = acc;
            red[tid] = W_nm[128 * 128 + tid] * attn[tid];  // w_b row . attn
        }
        __syncthreads();
        for (int s = 64; s > 0; s >>= 1) {
            if (tid < s) red[tid] += red[tid + s];
            __syncthreads();
        }
        if (tid == 0) g_c = red[0];
    } else {                               // 64 blocks: W_out1 -> fp16
        int i = (bid - 425) * 256 + tid;
        g_W1h[i] = __float2half_rn(W_out1[i]);
    }
}

__global__ void k2_hist(const int* __restrict__ dst) {
    int i = blockIdx.x * blockDim.x + threadIdx.x;
    if (i < EE) atomicAdd(&g_deg[dst[i]], 1);
}

// ---------------- k1: per-node A(fp16), B, a_s, a_d (persistent, NPW=4) ----
#define NPW 4
__global__ __launch_bounds__(256) void k1_node(
    const float* __restrict__ feat,
    const float* __restrict__ W1, const float* __restrict__ b1,
    const float* __restrict__ W_nm, const float* __restrict__ b_nm,
    const float* __restrict__ attn) {
    __shared__ __align__(16) float sW1[16 * 64];
    __shared__ __align__(16) float sW2h[64 * 128];
    __shared__ __align__(16) float sWf[16 * 128];
    __shared__ __align__(16) float sb1[64];
    __shared__ __align__(16) float sbnm[128];
    __shared__ __align__(16) float sbA[128];
    __shared__ __align__(16) float sattn[128];
    int tid = threadIdx.x;
    for (int i = tid; i < 16 * 64; i += 256) sW1[i] = W1[i];
    for (int i = tid; i < 64 * 128; i += 256) sW2h[i] = g_W2h[i];
    for (int i = tid; i < 16 * 128; i += 256) sWf[i] = W_nm[129 * 128 + i];
    if (tid < 64) sb1[tid] = b1[tid];
    if (tid < 128) { sbnm[tid] = b_nm[tid]; sbA[tid] = g_bA[tid]; sattn[tid] = attn[tid]; }
    __syncthreads();

    int warp = tid >> 5, lane = tid & 31;
    const unsigned FULL = 0xffffffffu;
    int l4 = 4 * lane;
    const int STRIDE = 8 * NPW;   // nodes per block per iteration

    for (int base = blockIdx.x * STRIDE; base < NN; base += gridDim.x * STRIDE) {
        int v0 = base + warp * NPW;
        if (v0 >= NN) continue;
        bool full = (v0 + NPW <= NN);

        float f[NPW];
#pragma unroll
        for (int i = 0; i < NPW; ++i) {
            int v = v0 + i;
            f[i] = (lane < 16 && (full || v < NN)) ? feat[(size_t)v * 16 + lane] : 0.f;
        }

        float u0[NPW], u1[NPW];
#pragma unroll
        for (int i = 0; i < NPW; ++i) { u0[i] = sb1[lane]; u1[i] = sb1[lane + 32]; }
#pragma unroll
        for (int k = 0; k < 16; ++k) {
            float w0 = sW1[k * 64 + lane];
            float w1 = sW1[k * 64 + lane + 32];
#pragma unroll
            for (int i = 0; i < NPW; ++i) {
                float fk = __shfl_sync(FULL, f[i], k);
                u0[i] = fmaf(fk, w0, u0[i]);
                u1[i] = fmaf(fk, w1, u1[i]);
            }
        }
#pragma unroll
        for (int i = 0; i < NPW; ++i) {
            u0[i] = lrelu(u0[i], 0.1f);
            u1[i] = lrelu(u1[i], 0.1f);
        }

        unsigned long long a0[NPW], a1[NPW];
#pragma unroll
        for (int i = 0; i < NPW; ++i) {
            a0[i] = pk2(sbA[l4], sbA[l4 + 1]);
            a1[i] = pk2(sbA[l4 + 2], sbA[l4 + 3]);
        }
#pragma unroll 8
        for (int k = 0; k < 64; ++k) {
            ulonglong2 w = *(const ulonglong2*)&sW2h[k * 128 + l4];
#pragma unroll
            for (int i = 0; i < NPW; ++i) {
                float uk = (k < 32) ? __shfl_sync(FULL, u0[i], k)
                                    : __shfl_sync(FULL, u1[i], k - 32);
                unsigned long long uu = pk2(uk, uk);
                a0[i] = fma2(uu, w.x, a0[i]);
                a1[i] = fma2(uu, w.y, a1[i]);
            }
        }
        float4 at = *(const float4*)&sattn[l4];
        float av4[NPW];
#pragma unroll
        for (int i = 0; i < NPW; ++i) {
            int v = v0 + i;
            if (!full && v >= NN) { av4[i] = 0.f; continue; }
            float2 x01 = upk2(a0[i]), x23 = upk2(a1[i]);
            __half2 h0 = __floats2half2_rn(x01.x, x01.y);
            __half2 h1 = __floats2half2_rn(x23.x, x23.y);
            uint2 hp;
            hp.x = *(unsigned*)&h0;
            hp.y = *(unsigned*)&h1;
            *(uint2*)&g_Ah[(size_t)v * 64 + 2 * lane] = hp;
            av4[i] = x01.x * at.x + x01.y * at.y + x23.x * at.z + x23.y * at.w;
        }

        unsigned long long c0[NPW], c1[NPW];
#pragma unroll
        for (int i = 0; i < NPW; ++i) {
            c0[i] = pk2(sbnm[l4], sbnm[l4 + 1]);
            c1[i] = pk2(sbnm[l4 + 2], sbnm[l4 + 3]);
        }
#pragma unroll
        for (int k = 0; k < 16; ++k) {
            ulonglong2 w = *(const ulonglong2*)&sWf[k * 128 + l4];
#pragma unroll
            for (int i = 0; i < NPW; ++i) {
                float fk = __shfl_sync(FULL, f[i], k);
                unsigned long long ff = pk2(fk, fk);
                c0[i] = fma2(ff, w.x, c0[i]);
                c1[i] = fma2(ff, w.y, c1[i]);
            }
        }
#pragma unroll
        for (int i = 0; i < NPW; ++i) {
            int v = v0 + i;
            if (!full && v >= NN) continue;
            float2 b01 = upk2(c0[i]), b23 = upk2(c1[i]);
            float4 b = make_float4(b01.x, b01.y, b23.x, b23.y);
            *(float4*)&g_B[(size_t)v * 128 + l4] = b;
            float ps = av4[i];
            float pd = b.x * at.x + b.y * at.y + b.z * at.z + b.w * at.w;
#pragma unroll
            for (int s = 16; s > 0; s >>= 1) {
                ps += __shfl_xor_sync(FULL, ps, s);
                pd += __shfl_xor_sync(FULL, pd, s);
            }
            if (lane == 0) { g_as[v] = ps; g_ad[v] = pd; }
        }
    }
}

// ---------------- kscan: decoupled-lookback scan, 4 elems/thread ------------
// padding degs are zero, so g_off[NN] (=EE) falls out automatically
__global__ __launch_bounds__(512) void kscan() {
    __shared__ int s[512];
    __shared__ int sh_run;
    int b = blockIdx.x, tid = threadIdx.x;
    int base = b * 2048 + tid * 4;
    int4 d4 = *(const int4*)&g_deg[base];
    int tsum = d4.x + d4.y + d4.z + d4.w;
    s[tid] = tsum;
    __syncthreads();
    for (int o = 1; o < 512; o <<= 1) {
        int t = (tid >= o) ? s[tid - o] : 0;
        __syncthreads();
        s[tid] += t;
        __syncthreads();
    }
    int incl = s[tid];
    int total = s[511];
    if (tid == 0) {
        g_sagg[b] = total;
        __threadfence();
        if (b == 0) {
            g_spref[0] = total;
            __threadfence();
            g_sstat[0] = 2;
            sh_run = 0;
        } else {
            g_sstat[b] = 1;
            int running = 0;
            int j = b - 1;
            while (true) {
                int st;
                while ((st = g_sstat[j]) == 0) { }
                if (st == 2) { running += g_spref[j]; break; }
                running += g_sagg[j];
                --j;
            }
            g_spref[b] = running + total;
            __threadfence();
            g_sstat[b] = 2;
            sh_run = running;
        }
    }
    __syncthreads();
    int e0 = incl - tsum + sh_run;
    int e1 = e0 + d4.x, e2 = e1 + d4.y, e3 = e2 + d4.z;
    int4 ev = make_int4(e0, e1, e2, e3);
    *(int4*)&g_off[base] = ev;
    *(int4*)&g_cur[base] = ev;
}

// scatter + edge logit + exp folded in
__global__ void k2_scatter(const int* __restrict__ src,
                           const int* __restrict__ dst,
                           const float* __restrict__ bit) {
    int i = blockIdx.x * blockDim.x + threadIdx.x;
    if (i < EE) {
        int s = src[i], d = dst[i];
        float bv = bit[i];
        float lg = g_as[s] + g_ad[d] + g_c * bv;
        lg = fmaxf(lg, 0.2f * lg);
        float ee = __expf(lg);
        int pos = atomicAdd(&g_cur[d], 1);
        g_srcv[pos] = s;
        g_lb[pos] = make_float2(ee, ee * bv);
    }
}

// ---------------- k3: softmax-agg + out MLP fused (warp per node) ----------
// SMEM-broadcast metadata/hn; W_out1 in fp16 (halves out-MLP L1 wavefronts)
__global__ __launch_bounds__(256, 4) void k3_fused(
    const float* __restrict__ W_nm,
    const float* __restrict__ b1,
    const float* __restrict__ W2, const float* __restrict__ b2,
    float* __restrict__ out) {
    __shared__ __align__(16) float sb1[128];
    __shared__ __align__(16) float sW2[128];
    __shared__ __align__(16) float swb[128];
    __shared__ __align__(8)  float2 smeta[8][32];   // (ee, src-as-float-bits)
    __shared__ __align__(16) float4 shn[8][32];     // staged hn per warp
    int tid = threadIdx.x;
    if (tid < 128) { sb1[tid] = b1[tid]; sW2[tid] = W2[tid]; swb[tid] = W_nm[128 * 128 + tid]; }
    __syncthreads();
    float b2v = b2[0];

    int warp = tid >> 5, lane = tid & 31;
    int l4 = 4 * lane;
    const unsigned FULL = 0xffffffffu;

    for (int base = blockIdx.x * 8; base < NN; base += gridDim.x * 8) {
        int v = base + warp;
        if (v >= NN) continue;

        int s0 = g_off[v], s1 = g_off[v + 1];
        float4 hn = make_float4(0.f, 0.f, 0.f, 0.f);
        if (s0 < s1) {
            unsigned long long acc0 = 0ull, acc1 = 0ull;
            float se = 0.f, st = 0.f;
            for (int cb = s0; cb < s1; cb += 32) {
                int n = min(32, s1 - cb);
                if (lane < n) {
                    int   sv = __ldg(&g_srcv[cb + lane]);
                    float2 lb = __ldg(&g_lb[cb + lane]);
                    se += lb.x;          // lane-parallel scalar sums
                    st += lb.y;
                    smeta[warp][lane] = make_float2(lb.x, __int_as_float(sv));
                }
                __syncwarp();
#pragma unroll 4
                for (int j = 0; j < n; ++j) {
                    float2 m = smeta[warp][j];      // broadcast LDS.64
                    float ee = m.x;
                    int   sv = __float_as_int(m.y);
                    uint2 raw = __ldg((const uint2*)&g_Ah[(size_t)sv * 64 + 2 * lane]);
                    float2 f0 = __half22float2(*(__half2*)&raw.x);
                    float2 f1 = __half22float2(*(__half2*)&raw.y);
                    unsigned long long ev = pk2(ee, ee);
                    acc0 = fma2(ev, pk2(f0.x, f0.y), acc0);
                    acc1 = fma2(ev, pk2(f1.x, f1.y), acc1);
                }
                __syncwarp();
            }
#pragma unroll
            for (int o = 16; o > 0; o >>= 1) {
                se += __shfl_xor_sync(FULL, se, o);
                st += __shfl_xor_sync(FULL, st, o);
            }
            float inv = 1.f / se;
            float tb = st * inv;
            float2 a01 = upk2(acc0), a23 = upk2(acc1);
            float4 B4 = __ldg((const float4*)&g_B[(size_t)v * 128 + l4]);
            float4 wb = *(const float4*)&swb[l4];
            hn.x = fmaxf(fmaf(a01.x, inv, B4.x) + wb.x * tb, 0.f);
            hn.y = fmaxf(fmaf(a01.y, inv, B4.y) + wb.y * tb, 0.f);
            hn.z = fmaxf(fmaf(a23.x, inv, B4.z) + wb.z * tb, 0.f);
            hn.w = fmaxf(fmaf(a23.y, inv, B4.w) + wb.w * tb, 0.f);
        }

        // out MLP: acc = lrelu(hn @ W_out1 + b_out1); out = acc . W_out2 + b2
        shn[warp][lane] = hn;
        __syncwarp();
        unsigned long long o0 = pk2(sb1[l4], sb1[l4 + 1]);
        unsigned long long o1 = pk2(sb1[l4 + 2], sb1[l4 + 3]);
#pragma unroll 4
        for (int kg = 0; kg < 32; ++kg) {
            float4 h4 = shn[warp][kg];              // broadcast LDS.128
#pragma unroll
            for (int c = 0; c < 4; ++c) {
                float val = (c == 0) ? h4.x : (c == 1) ? h4.y : (c == 2) ? h4.z : h4.w;
                if (val != 0.f) {                   // warp-uniform (same value all lanes)
                    uint2 w = __ldg((const uint2*)&g_W1h[(kg * 4 + c) * 128 + l4]);
                    float2 w01 = __half22float2(*(__half2*)&w.x);
                    float2 w23 = __half22float2(*(__half2*)&w.y);
                    unsigned long long vv = pk2(val, val);
                    o0 = fma2(vv, pk2(w01.x, w01.y), o0);
                    o1 = fma2(vv, pk2(w23.x, w23.y), o1);
                }
            }
        }
        __syncwarp();
        float2 q01 = upk2(o0), q23 = upk2(o1);
        float4 acc = make_float4(lrelu(q01.x, 0.1f), lrelu(q01.y, 0.1f),
                                 lrelu(q23.x, 0.1f), lrelu(q23.y, 0.1f));
        float4 w2 = *(const float4*)&sW2[l4];
        float p = acc.x * w2.x + acc.y * w2.y + acc.z * w2.z + acc.w * w2.w;
#pragma unroll
        for (int o = 16; o > 0; o >>= 1) p += __shfl_xor_sync(FULL, p, o);
        if (lane == 0) out[v] = p + b2v;
    }
}

// ---------------- launch -----------------------------------------------------
extern "C" void kernel_launch(void* const* d_in, const int* in_sizes, int n_in,
                              void* d_out, int out_size) {
    const float* feat    = (const float*)d_in[0];
    const float* bit     = (const float*)d_in[1];
    const int*   src     = (const int*)d_in[2];
    const int*   dst     = (const int*)d_in[3];
    const float* W_self1 = (const float*)d_in[4];
    const float* b_self1 = (const float*)d_in[5];
    const float* W_self2 = (const float*)d_in[6];
    const float* b_self2 = (const float*)d_in[7];
    const float* W_nm    = (const float*)d_in[8];
    const float* b_nm    = (const float*)d_in[9];
    const float* attn    = (const float*)d_in[10];
    const float* W_out1  = (const float*)d_in[11];
    const float* b_out1  = (const float*)d_in[12];
    const float* W_out2  = (const float*)d_in[13];
    const float* b_out2  = (const float*)d_in[14];
    float* out = (float*)d_out;

    f0_init<<<489, 256>>>(W_self2, b_self2, W_nm, attn, W_out1);
    k2_hist<<<(EE + 255) / 256, 256>>>(dst);
    k1_node<<<592, 256>>>(feat, W_self1, b_self1, W_nm, b_nm, attn);
    kscan<<<NSB, 512>>>();
    k2_scatter<<<(EE + 255) / 256, 256>>>(src, dst, bit);
    k3_fused<<<592, 256>>>(W_nm, b_out1, W_out2, b_out2, out);
}

// round 15
// speedup vs baseline: 1.1537x; 1.1537x over previous
#include <cuda_runtime.h>
#include <cuda_fp16.h>
#include <math.h>

#define NN 100000
#define NP 100352         // NN padded to 2048 multiple (scan tiles)
#define EE 1600000
#define FF 16
#define HH 128
#define NSB 49            // scan blocks: ceil(NP/2048)

// ---------------- scratch (device globals; no allocation allowed) ----------
__device__ __align__(16) __half2 g_Ah[(size_t)NN * 64];  // h @ W_h (fp16, 256B/row)
__device__ __align__(16) float g_B[(size_t)NN * HH];     // feat @ W_f + b_nm
__device__ float g_as[NN];
__device__ float g_ad[NN];
__device__ __align__(16) int g_deg[NP];
__device__ __align__(16) int g_off[NP];
__device__ __align__(16) int g_cur[NP];
__device__ volatile int g_sstat[NSB];            // 0=invalid 1=agg 2=prefix
__device__ volatile int g_sagg[NSB];
__device__ volatile int g_spref[NSB];
__device__ __align__(16) int4 g_elb[EE];        // CSR-ordered (src, ee, ee*bit, pad)
__device__ __align__(16) float g_W2h[64 * HH];
__device__ __align__(16) float g_bA[HH];
__device__ float g_c;

__device__ __forceinline__ float lrelu(float x, float s) { return fmaxf(x, s * x); }

// packed fp32x2 helpers (Blackwell FFMA2: 2x fp32 FMA issue rate)
__device__ __forceinline__ unsigned long long pk2(float x, float y) {
    unsigned long long r; asm("mov.b64 %0,{%1,%2};" : "=l"(r) : "f"(x), "f"(y)); return r;
}
__device__ __forceinline__ float2 upk2(unsigned long long v) {
    float2 r; asm("mov.b64 {%0,%1},%2;" : "=f"(r.x), "=f"(r.y) : "l"(v)); return r;
}
__device__ __forceinline__ unsigned long long fma2(unsigned long long a,
                                                   unsigned long long b,
                                                   unsigned long long c) {
    unsigned long long d;
    asm("fma.rn.f32x2 %0,%1,%2,%3;" : "=l"(d) : "l"(a), "l"(b), "l"(c));
    return d;
}

// ---------------- f0: zero deg/status + W2h fold + bias + c -----------------
__global__ __launch_bounds__(256) void f0_init(
    const float* __restrict__ W_self2, const float* __restrict__ b_self2,
    const float* __restrict__ W_nm, const float* __restrict__ attn) {
    int bid = blockIdx.x, tid = threadIdx.x;
    if (bid < 392) {                       // zero g_deg (incl. padding) + statuses
        int i = bid * 256 + tid;
        if (i < NP) g_deg[i] = 0;
        if (bid == 0 && tid < NSB) g_sstat[tid] = 0;
    } else if (bid < 424) {                // 32 blocks: 2 rows of W2h each
        int i = (bid - 392) * 2 + (tid >> 7);
        int j = tid & 127;
        float acc = 0.f;
        for (int k = 0; k < 128; ++k)
            acc = fmaf(W_self2[i * 128 + k], W_nm[k * 128 + j], acc);
        g_W2h[i * 128 + j] = acc;
    } else {                               // bias fold + scalar c
        __shared__ float red[128];
        if (tid < 128) {
            float acc = 0.f;
            for (int k = 0; k < 128; ++k)
                acc = fmaf(b_self2[k], W_nm[k * 128 + tid], acc);
            g_bA[tid] = acc;
            red[tid] = W_nm[128 * 128 + tid] * attn[tid];  // w_b row . attn
        }
        __syncthreads();
        for (int s = 64; s > 0; s >>= 1) {
            if (tid < s) red[tid] += red[tid + s];
            __syncthreads();
        }
        if (tid == 0) g_c = red[0];
    }
}

__global__ void k2_hist(const int* __restrict__ dst) {
    int i = blockIdx.x * blockDim.x + threadIdx.x;
    if (i < EE) atomicAdd(&g_deg[dst[i]], 1);
}

// ---------------- k1: per-node A(fp16), B, a_s, a_d (persistent, NPW=4) ----
#define NPW 4
__global__ __launch_bounds__(256) void k1_node(
    const float* __restrict__ feat,
    const float* __restrict__ W1, const float* __restrict__ b1,
    const float* __restrict__ W_nm, const float* __restrict__ b_nm,
    const float* __restrict__ attn) {
    __shared__ __align__(16) float sW1[16 * 64];
    __shared__ __align__(16) float sW2h[64 * 128];
    __shared__ __align__(16) float sWf[16 * 128];
    __shared__ __align__(16) float sb1[64];
    __shared__ __align__(16) float sbnm[128];
    __shared__ __align__(16) float sbA[128];
    __shared__ __align__(16) float sattn[128];
    int tid = threadIdx.x;
    for (int i = tid; i < 16 * 64; i += 256) sW1[i] = W1[i];
    for (int i = tid; i < 64 * 128; i += 256) sW2h[i] = g_W2h[i];
    for (int i = tid; i < 16 * 128; i += 256) sWf[i] = W_nm[129 * 128 + i];
    if (tid < 64) sb1[tid] = b1[tid];
    if (tid < 128) { sbnm[tid] = b_nm[tid]; sbA[tid] = g_bA[tid]; sattn[tid] = attn[tid]; }
    __syncthreads();

    int warp = tid >> 5, lane = tid & 31;
    const unsigned FULL = 0xffffffffu;
    int l4 = 4 * lane;
    const int STRIDE = 8 * NPW;   // nodes per block per iteration

    for (int base = blockIdx.x * STRIDE; base < NN; base += gridDim.x * STRIDE) {
        int v0 = base + warp * NPW;
        if (v0 >= NN) continue;
        bool full = (v0 + NPW <= NN);

        float f[NPW];
#pragma unroll
        for (int i = 0; i < NPW; ++i) {
            int v = v0 + i;
            f[i] = (lane < 16 && (full || v < NN)) ? feat[(size_t)v * 16 + lane] : 0.f;
        }

        float u0[NPW], u1[NPW];
#pragma unroll
        for (int i = 0; i < NPW; ++i) { u0[i] = sb1[lane]; u1[i] = sb1[lane + 32]; }
#pragma unroll
        for (int k = 0; k < 16; ++k) {
            float w0 = sW1[k * 64 + lane];
            float w1 = sW1[k * 64 + lane + 32];
#pragma unroll
            for (int i = 0; i < NPW; ++i) {
                float fk = __shfl_sync(FULL, f[i], k);
                u0[i] = fmaf(fk, w0, u0[i]);
                u1[i] = fmaf(fk, w1, u1[i]);
            }
        }
#pragma unroll
        for (int i = 0; i < NPW; ++i) {
            u0[i] = lrelu(u0[i], 0.1f);
            u1[i] = lrelu(u1[i], 0.1f);
        }

        unsigned long long a0[NPW], a1[NPW];
#pragma unroll
        for (int i = 0; i < NPW; ++i) {
            a0[i] = pk2(sbA[l4], sbA[l4 + 1]);
            a1[i] = pk2(sbA[l4 + 2], sbA[l4 + 3]);
        }
#pragma unroll 8
        for (int k = 0; k < 64; ++k) {
            ulonglong2 w = *(const ulonglong2*)&sW2h[k * 128 + l4];
#pragma unroll
            for (int i = 0; i < NPW; ++i) {
                float uk = (k < 32) ? __shfl_sync(FULL, u0[i], k)
                                    : __shfl_sync(FULL, u1[i], k - 32);
                unsigned long long uu = pk2(uk, uk);
                a0[i] = fma2(uu, w.x, a0[i]);
                a1[i] = fma2(uu, w.y, a1[i]);
            }
        }
        float4 at = *(const float4*)&sattn[l4];
        float av4[NPW];
#pragma unroll
        for (int i = 0; i < NPW; ++i) {
            int v = v0 + i;
            if (!full && v >= NN) { av4[i] = 0.f; continue; }
            float2 x01 = upk2(a0[i]), x23 = upk2(a1[i]);
            __half2 h0 = __floats2half2_rn(x01.x, x01.y);
            __half2 h1 = __floats2half2_rn(x23.x, x23.y);
            uint2 hp;
            hp.x = *(unsigned*)&h0;
            hp.y = *(unsigned*)&h1;
            *(uint2*)&g_Ah[(size_t)v * 64 + 2 * lane] = hp;
            av4[i] = x01.x * at.x + x01.y * at.y + x23.x * at.z + x23.y * at.w;
        }

        unsigned long long c0[NPW], c1[NPW];
#pragma unroll
        for (int i = 0; i < NPW; ++i) {
            c0[i] = pk2(sbnm[l4], sbnm[l4 + 1]);
            c1[i] = pk2(sbnm[l4 + 2], sbnm[l4 + 3]);
        }
#pragma unroll
        for (int k = 0; k < 16; ++k) {
            ulonglong2 w = *(const ulonglong2*)&sWf[k * 128 + l4];
#pragma unroll
            for (int i = 0; i < NPW; ++i) {
                float fk = __shfl_sync(FULL, f[i], k);
                unsigned long long ff = pk2(fk, fk);
                c0[i] = fma2(ff, w.x, c0[i]);
                c1[i] = fma2(ff, w.y, c1[i]);
            }
        }
#pragma unroll
        for (int i = 0; i < NPW; ++i) {
            int v = v0 + i;
            if (!full && v >= NN) continue;
            float2 b01 = upk2(c0[i]), b23 = upk2(c1[i]);
            float4 b = make_float4(b01.x, b01.y, b23.x, b23.y);
            *(float4*)&g_B[(size_t)v * 128 + l4] = b;
            float ps = av4[i];
            float pd = b.x * at.x + b.y * at.y + b.z * at.z + b.w * at.w;
#pragma unroll
            for (int s = 16; s > 0; s >>= 1) {
                ps += __shfl_xor_sync(FULL, ps, s);
                pd += __shfl_xor_sync(FULL, pd, s);
            }
            if (lane == 0) { g_as[v] = ps; g_ad[v] = pd; }
        }
    }
}

// ---------------- kscan: decoupled-lookback scan, 4 elems/thread ------------
__global__ __launch_bounds__(512) void kscan() {
    __shared__ int s[512];
    __shared__ int sh_run;
    int b = blockIdx.x, tid = threadIdx.x;
    int base = b * 2048 + tid * 4;
    int4 d4 = *(const int4*)&g_deg[base];
    int tsum = d4.x + d4.y + d4.z + d4.w;
    s[tid] = tsum;
    __syncthreads();
    for (int o = 1; o < 512; o <<= 1) {
        int t = (tid >= o) ? s[tid - o] : 0;
        __syncthreads();
        s[tid] += t;
        __syncthreads();
    }
    int incl = s[tid];
    int total = s[511];
    if (tid == 0) {
        g_sagg[b] = total;
        __threadfence();
        if (b == 0) {
            g_spref[0] = total;
            __threadfence();
            g_sstat[0] = 2;
            sh_run = 0;
        } else {
            g_sstat[b] = 1;
            int running = 0;
            int j = b - 1;
            while (true) {
                int st;
                while ((st = g_sstat[j]) == 0) { }
                if (st == 2) { running += g_spref[j]; break; }
                running += g_sagg[j];
                --j;
            }
            g_spref[b] = running + total;
            __threadfence();
            g_sstat[b] = 2;
            sh_run = running;
        }
    }
    __syncthreads();
    int e0 = incl - tsum + sh_run;
    int e1 = e0 + d4.x, e2 = e1 + d4.y, e3 = e2 + d4.z;
    int4 ev = make_int4(e0, e1, e2, e3);
    *(int4*)&g_off[base] = ev;
    *(int4*)&g_cur[base] = ev;
}

// scatter + edge logit + exp; single 16B record per edge (1 random sector)
__global__ void k2_scatter(const int* __restrict__ src,
                           const int* __restrict__ dst,
                           const float* __restrict__ bit) {
    int i = blockIdx.x * blockDim.x + threadIdx.x;
    if (i < EE) {
        int s = src[i], d = dst[i];
        float bv = bit[i];
        float lg = g_as[s] + g_ad[d] + g_c * bv;
        lg = fmaxf(lg, 0.2f * lg);
        float ee = __expf(lg);
        int pos = atomicAdd(&g_cur[d], 1);
        g_elb[pos] = make_int4(s, __float_as_int(ee), __float_as_int(ee * bv), 0);
    }
}

// ---------------- k3: softmax-agg + out MLP fused (warp per node) ----------
// SMEM-broadcast metadata/hn; W_out1 fp32 via __ldg (fp16 rejected: R8/R14)
__global__ __launch_bounds__(256, 4) void k3_fused(
    const float* __restrict__ W_nm,
    const float* __restrict__ W1, const float* __restrict__ b1,
    const float* __restrict__ W2, const float* __restrict__ b2,
    float* __restrict__ out) {
    __shared__ __align__(16) float sb1[128];
    __shared__ __align__(16) float sW2[128];
    __shared__ __align__(16) float swb[128];
    __shared__ __align__(8)  float2 smeta[8][32];   // (ee, src-as-float-bits)
    __shared__ __align__(16) float4 shn[8][32];     // staged hn per warp
    int tid = threadIdx.x;
    if (tid < 128) { sb1[tid] = b1[tid]; sW2[tid] = W2[tid]; swb[tid] = W_nm[128 * 128 + tid]; }
    __syncthreads();
    float b2v = b2[0];

    int warp = tid >> 5, lane = tid & 31;
    int l4 = 4 * lane;
    const unsigned FULL = 0xffffffffu;

    for (int base = blockIdx.x * 8; base < NN; base += gridDim.x * 8) {
        int v = base + warp;
        if (v >= NN) continue;

        int s0 = g_off[v], s1 = g_off[v + 1];
        float4 hn = make_float4(0.f, 0.f, 0.f, 0.f);
        if (s0 < s1) {
            unsigned long long acc0 = 0ull, acc1 = 0ull;
            float se = 0.f, st = 0.f;
            for (int cb = s0; cb < s1; cb += 32) {
                int n = min(32, s1 - cb);
                if (lane < n) {
                    int4 md = __ldg(&g_elb[cb + lane]);   // one coalesced LDG.128
                    float ee = __int_as_float(md.y);
                    se += ee;                              // lane-parallel scalar sums
                    st += __int_as_float(md.z);
                    smeta[warp][lane] = make_float2(ee, __int_as_float(md.x));
                }
                __syncwarp();
#pragma unroll 4
                for (int j = 0; j < n; ++j) {
                    float2 m = smeta[warp][j];      // broadcast LDS.64
                    float ee = m.x;
                    int   sv = __float_as_int(m.y);
                    uint2 raw = __ldg((const uint2*)&g_Ah[(size_t)sv * 64 + 2 * lane]);
                    float2 f0 = __half22float2(*(__half2*)&raw.x);
                    float2 f1 = __half22float2(*(__half2*)&raw.y);
                    unsigned long long ev = pk2(ee, ee);
                    acc0 = fma2(ev, pk2(f0.x, f0.y), acc0);
                    acc1 = fma2(ev, pk2(f1.x, f1.y), acc1);
                }
                __syncwarp();
            }
#pragma unroll
            for (int o = 16; o > 0; o >>= 1) {
                se += __shfl_xor_sync(FULL, se, o);
                st += __shfl_xor_sync(FULL, st, o);
            }
            float inv = 1.f / se;
            float tb = st * inv;
            float2 a01 = upk2(acc0), a23 = upk2(acc1);
            float4 B4 = __ldg((const float4*)&g_B[(size_t)v * 128 + l4]);
            float4 wb = *(const float4*)&swb[l4];
            hn.x = fmaxf(fmaf(a01.x, inv, B4.x) + wb.x * tb, 0.f);
            hn.y = fmaxf(fmaf(a01.y, inv, B4.y) + wb.y * tb, 0.f);
            hn.z = fmaxf(fmaf(a23.x, inv, B4.z) + wb.z * tb, 0.f);
            hn.w = fmaxf(fmaf(a23.y, inv, B4.w) + wb.w * tb, 0.f);
        }

        // out MLP: acc = lrelu(hn @ W_out1 + b_out1); out = acc . W_out2 + b2
        shn[warp][lane] = hn;
        __syncwarp();
        unsigned long long o0 = pk2(sb1[l4], sb1[l4 + 1]);
        unsigned long long o1 = pk2(sb1[l4 + 2], sb1[l4 + 3]);
#pragma unroll 4
        for (int kg = 0; kg < 32; ++kg) {
            float4 h4 = shn[warp][kg];              // broadcast LDS.128
#pragma unroll
            for (int c = 0; c < 4; ++c) {
                float val = (c == 0) ? h4.x : (c == 1) ? h4.y : (c == 2) ? h4.z : h4.w;
                if (val != 0.f) {                   // warp-uniform (same value all lanes)
                    ulonglong2 w = __ldg((const ulonglong2*)&W1[(kg * 4 + c) * 128 + l4]);
                    unsigned long long vv = pk2(val, val);
                    o0 = fma2(vv, w.x, o0);
                    o1 = fma2(vv, w.y, o1);
                }
            }
        }
        __syncwarp();
        float2 q01 = upk2(o0), q23 = upk2(o1);
        float4 acc = make_float4(lrelu(q01.x, 0.1f), lrelu(q01.y, 0.1f),
                                 lrelu(q23.x, 0.1f), lrelu(q23.y, 0.1f));
        float4 w2 = *(const float4*)&sW2[l4];
        float p = acc.x * w2.x + acc.y * w2.y + acc.z * w2.z + acc.w * w2.w;
#pragma unroll
        for (int o = 16; o > 0; o >>= 1) p += __shfl_xor_sync(FULL, p, o);
        if (lane == 0) out[v] = p + b2v;
    }
}

// ---------------- launch -----------------------------------------------------
extern "C" void kernel_launch(void* const* d_in, const int* in_sizes, int n_in,
                              void* d_out, int out_size) {
    const float* feat    = (const float*)d_in[0];
    const float* bit     = (const float*)d_in[1];
    const int*   src     = (const int*)d_in[2];
    const int*   dst     = (const int*)d_in[3];
    const float* W_self1 = (const float*)d_in[4];
    const float* b_self1 = (const float*)d_in[5];
    const float* W_self2 = (const float*)d_in[6];
    const float* b_self2 = (const float*)d_in[7];
    const float* W_nm    = (const float*)d_in[8];
    const float* b_nm    = (const float*)d_in[9];
    const float* attn    = (const float*)d_in[10];
    const float* W_out1  = (const float*)d_in[11];
    const float* b_out1  = (const float*)d_in[12];
    const float* W_out2  = (const float*)d_in[13];
    const float* b_out2  = (const float*)d_in[14];
    float* out = (float*)d_out;

    f0_init<<<425, 256>>>(W_self2, b_self2, W_nm, attn);
    k2_hist<<<(EE + 255) / 256, 256>>>(dst);
    k1_node<<<592, 256>>>(feat, W_self1, b_self1, W_nm, b_nm, attn);
    kscan<<<NSB, 512>>>();
    k2_scatter<<<(EE + 255) / 256, 256>>>(src, dst, bit);
    k3_fused<<<592, 256>>>(W_nm, W_out1, b_out1, W_out2, b_out2, out);
}

// round 16
// speedup vs baseline: 1.2017x; 1.0417x over previous
#include <cuda_runtime.h>
#include <cuda_fp16.h>
#include <math.h>

#define NN 100000
#define NP 100352         // NN padded to 2048 multiple (scan tiles)
#define EE 1600000
#define FF 16
#define HH 128
#define NSB 49            // scan blocks: ceil(NP/2048)
#define NB1 592           // k1 persistent blocks
#define NEB 2703          // hist edges per k1 block (592*2703 >= EE)

// ---------------- scratch (device globals; zero-init at module load) -------
__device__ __align__(16) __half2 g_Ah[(size_t)NN * 64];  // h @ W_h (fp16, 256B/row)
__device__ __align__(16) float g_B[(size_t)NN * HH];     // feat @ W_f + b_nm
__device__ float g_as[NN];
__device__ float g_ad[NN];
__device__ __align__(16) int g_deg[NP];   // ZERO invariant: reset by k3 each run
__device__ __align__(16) int g_off[NP];
__device__ __align__(16) int g_cur[NP];
__device__ volatile int g_sstat[NSB];     // ZERO invariant: reset by scatter
__device__ volatile int g_sagg[NSB];
__device__ volatile int g_spref[NSB];
__device__ __align__(16) int4 g_elb[EE];  // CSR-ordered (src, ee, ee*bit, pad)
__device__ __align__(16) float g_W2h[64 * HH];
__device__ __align__(16) float g_bA[HH];
__device__ float g_c;

__device__ __forceinline__ float lrelu(float x, float s) { return fmaxf(x, s * x); }

// packed fp32x2 helpers (Blackwell FFMA2: 2x fp32 FMA per issue slot)
__device__ __forceinline__ unsigned long long pk2(float x, float y) {
    unsigned long long r; asm("mov.b64 %0,{%1,%2};" : "=l"(r) : "f"(x), "f"(y)); return r;
}
__device__ __forceinline__ float2 upk2(unsigned long long v) {
    float2 r; asm("mov.b64 {%0,%1},%2;" : "=f"(r.x), "=f"(r.y) : "l"(v)); return r;
}
__device__ __forceinline__ unsigned long long fma2(unsigned long long a,
                                                   unsigned long long b,
                                                   unsigned long long c) {
    unsigned long long d;
    asm("fma.rn.f32x2 %0,%1,%2,%3;" : "=l"(d) : "l"(a), "l"(b), "l"(c));
    return d;
}

// ---------------- f0w: W2h fold + bias + c (weights only, 33 blocks) -------
__global__ __launch_bounds__(256) void f0w(
    const float* __restrict__ W_self2, const float* __restrict__ b_self2,
    const float* __restrict__ W_nm, const float* __restrict__ attn) {
    int bid = blockIdx.x, tid = threadIdx.x;
    if (bid < 32) {                        // 2 rows of W2h per block
        int i = bid * 2 + (tid >> 7);
        int j = tid & 127;
        float acc = 0.f;
        for (int k = 0; k < 128; ++k)
            acc = fmaf(W_self2[i * 128 + k], W_nm[k * 128 + j], acc);
        g_W2h[i * 128 + j] = acc;
    } else {                               // bias fold + scalar c
        __shared__ float red[128];
        if (tid < 128) {
            float acc = 0.f;
            for (int k = 0; k < 128; ++k)
                acc = fmaf(b_self2[k], W_nm[k * 128 + tid], acc);
            g_bA[tid] = acc;
            red[tid] = W_nm[128 * 128 + tid] * attn[tid];  // w_b row . attn
        }
        __syncthreads();
        for (int s = 64; s > 0; s >>= 1) {
            if (tid < s) red[tid] += red[tid + s];
            __syncthreads();
        }
        if (tid == 0) g_c = red[0];
    }
}

// ---------------- k1h: hist slice + per-node A(fp16), B, a_s, a_d ----------
// hist atomics (fire-and-forget RED) overlap the SMEM weight staging
#define NPW 4
__global__ __launch_bounds__(256) void k1h(
    const float* __restrict__ feat, const int* __restrict__ dst,
    const float* __restrict__ W1, const float* __restrict__ b1,
    const float* __restrict__ W_nm, const float* __restrict__ b_nm,
    const float* __restrict__ attn) {
    __shared__ __align__(16) float sW1[16 * 64];
    __shared__ __align__(16) float sW2h[64 * 128];
    __shared__ __align__(16) float sWf[16 * 128];
    __shared__ __align__(16) float sb1[64];
    __shared__ __align__(16) float sbnm[128];
    __shared__ __align__(16) float sbA[128];
    __shared__ __align__(16) float sattn[128];
    int tid = threadIdx.x;

    // histogram slice (g_deg is zero on entry: module init / k3 reset)
    {
        int e0 = blockIdx.x * NEB;
        int e1 = min(EE, e0 + NEB);
        for (int e = e0 + tid; e < e1; e += 256)
            atomicAdd(&g_deg[dst[e]], 1);
    }

    for (int i = tid; i < 16 * 64; i += 256) sW1[i] = W1[i];
    for (int i = tid; i < 64 * 128; i += 256) sW2h[i] = g_W2h[i];
    for (int i = tid; i < 16 * 128; i += 256) sWf[i] = W_nm[129 * 128 + i];
    if (tid < 64) sb1[tid] = b1[tid];
    if (tid < 128) { sbnm[tid] = b_nm[tid]; sbA[tid] = g_bA[tid]; sattn[tid] = attn[tid]; }
    __syncthreads();

    int warp = tid >> 5, lane = tid & 31;
    const unsigned FULL = 0xffffffffu;
    int l4 = 4 * lane;
    const int STRIDE = 8 * NPW;

    for (int base = blockIdx.x * STRIDE; base < NN; base += gridDim.x * STRIDE) {
        int v0 = base + warp * NPW;
        if (v0 >= NN) continue;
        bool full = (v0 + NPW <= NN);

        float f[NPW];
#pragma unroll
        for (int i = 0; i < NPW; ++i) {
            int v = v0 + i;
            f[i] = (lane < 16 && (full || v < NN)) ? feat[(size_t)v * 16 + lane] : 0.f;
        }

        float u0[NPW], u1[NPW];
#pragma unroll
        for (int i = 0; i < NPW; ++i) { u0[i] = sb1[lane]; u1[i] = sb1[lane + 32]; }
#pragma unroll
        for (int k = 0; k < 16; ++k) {
            float w0 = sW1[k * 64 + lane];
            float w1 = sW1[k * 64 + lane + 32];
#pragma unroll
            for (int i = 0; i < NPW; ++i) {
                float fk = __shfl_sync(FULL, f[i], k);
                u0[i] = fmaf(fk, w0, u0[i]);
                u1[i] = fmaf(fk, w1, u1[i]);
            }
        }
#pragma unroll
        for (int i = 0; i < NPW; ++i) {
            u0[i] = lrelu(u0[i], 0.1f);
            u1[i] = lrelu(u1[i], 0.1f);
        }

        unsigned long long a0[NPW], a1[NPW];
#pragma unroll
        for (int i = 0; i < NPW; ++i) {
            a0[i] = pk2(sbA[l4], sbA[l4 + 1]);
            a1[i] = pk2(sbA[l4 + 2], sbA[l4 + 3]);
        }
#pragma unroll 8
        for (int k = 0; k < 64; ++k) {
            ulonglong2 w = *(const ulonglong2*)&sW2h[k * 128 + l4];
#pragma unroll
            for (int i = 0; i < NPW; ++i) {
                float uk = (k < 32) ? __shfl_sync(FULL, u0[i], k)
                                    : __shfl_sync(FULL, u1[i], k - 32);
                unsigned long long uu = pk2(uk, uk);
                a0[i] = fma2(uu, w.x, a0[i]);
                a1[i] = fma2(uu, w.y, a1[i]);
            }
        }
        float4 at = *(const float4*)&sattn[l4];
        float av4[NPW];
#pragma unroll
        for (int i = 0; i < NPW; ++i) {
            int v = v0 + i;
            if (!full && v >= NN) { av4[i] = 0.f; continue; }
            float2 x01 = upk2(a0[i]), x23 = upk2(a1[i]);
            __half2 h0 = __floats2half2_rn(x01.x, x01.y);
            __half2 h1 = __floats2half2_rn(x23.x, x23.y);
            uint2 hp;
            hp.x = *(unsigned*)&h0;
            hp.y = *(unsigned*)&h1;
            *(uint2*)&g_Ah[(size_t)v * 64 + 2 * lane] = hp;
            av4[i] = x01.x * at.x + x01.y * at.y + x23.x * at.z + x23.y * at.w;
        }

        unsigned long long c0[NPW], c1[NPW];
#pragma unroll
        for (int i = 0; i < NPW; ++i) {
            c0[i] = pk2(sbnm[l4], sbnm[l4 + 1]);
            c1[i] = pk2(sbnm[l4 + 2], sbnm[l4 + 3]);
        }
#pragma unroll
        for (int k = 0; k < 16; ++k) {
            ulonglong2 w = *(const ulonglong2*)&sWf[k * 128 + l4];
#pragma unroll
            for (int i = 0; i < NPW; ++i) {
                float fk = __shfl_sync(FULL, f[i], k);
                unsigned long long ff = pk2(fk, fk);
                c0[i] = fma2(ff, w.x, c0[i]);
                c1[i] = fma2(ff, w.y, c1[i]);
            }
        }
#pragma unroll
        for (int i = 0; i < NPW; ++i) {
            int v = v0 + i;
            if (!full && v >= NN) continue;
            float2 b01 = upk2(c0[i]), b23 = upk2(c1[i]);
            float4 b = make_float4(b01.x, b01.y, b23.x, b23.y);
            *(float4*)&g_B[(size_t)v * 128 + l4] = b;
            float ps = av4[i];
            float pd = b.x * at.x + b.y * at.y + b.z * at.z + b.w * at.w;
#pragma unroll
            for (int s = 16; s > 0; s >>= 1) {
                ps += __shfl_xor_sync(FULL, ps, s);
                pd += __shfl_xor_sync(FULL, pd, s);
            }
            if (lane == 0) { g_as[v] = ps; g_ad[v] = pd; }
        }
    }
}

// ---------------- kscan: decoupled-lookback scan, 4 elems/thread ------------
__global__ __launch_bounds__(512) void kscan() {
    __shared__ int s[512];
    __shared__ int sh_run;
    int b = blockIdx.x, tid = threadIdx.x;
    int base = b * 2048 + tid * 4;
    int4 d4 = *(const int4*)&g_deg[base];
    int tsum = d4.x + d4.y + d4.z + d4.w;
    s[tid] = tsum;
    __syncthreads();
    for (int o = 1; o < 512; o <<= 1) {
        int t = (tid >= o) ? s[tid - o] : 0;
        __syncthreads();
        s[tid] += t;
        __syncthreads();
    }
    int incl = s[tid];
    int total = s[511];
    if (tid == 0) {
        g_sagg[b] = total;
        __threadfence();
        if (b == 0) {
            g_spref[0] = total;
            __threadfence();
            g_sstat[0] = 2;
            sh_run = 0;
        } else {
            g_sstat[b] = 1;
            int running = 0;
            int j = b - 1;
            while (true) {
                int st;
                while ((st = g_sstat[j]) == 0) { }
                if (st == 2) { running += g_spref[j]; break; }
                running += g_sagg[j];
                --j;
            }
            g_spref[b] = running + total;
            __threadfence();
            g_sstat[b] = 2;
            sh_run = running;
        }
    }
    __syncthreads();
    int e0 = incl - tsum + sh_run;
    int e1 = e0 + d4.x, e2 = e1 + d4.y, e3 = e2 + d4.z;
    int4 ev = make_int4(e0, e1, e2, e3);
    *(int4*)&g_off[base] = ev;
    *(int4*)&g_cur[base] = ev;
}

// scatter + edge logit + exp; 16B record/edge; resets scan statuses for next run
__global__ void k2_scatter(const int* __restrict__ src,
                           const int* __restrict__ dst,
                           const float* __restrict__ bit) {
    if (blockIdx.x == 0 && threadIdx.x < NSB) g_sstat[threadIdx.x] = 0;
    int i = blockIdx.x * blockDim.x + threadIdx.x;
    if (i < EE) {
        int s = src[i], d = dst[i];
        float bv = bit[i];
        float lg = g_as[s] + g_ad[d] + g_c * bv;
        lg = fmaxf(lg, 0.2f * lg);
        float ee = __expf(lg);
        int pos = atomicAdd(&g_cur[d], 1);
        g_elb[pos] = make_int4(s, __float_as_int(ee), __float_as_int(ee * bv), 0);
    }
}

// ---------------- k3: softmax-agg + out MLP fused (4 nodes per warp) -------
// Out-MLP amortizes each W1 row load + zero-test over 4 nodes.
__global__ __launch_bounds__(256, 4) void k3_fused(
    const float* __restrict__ W_nm,
    const float* __restrict__ W1, const float* __restrict__ b1,
    const float* __restrict__ W2, const float* __restrict__ b2,
    float* __restrict__ out) {
    __shared__ __align__(16) float sb1[128];
    __shared__ __align__(16) float sW2[128];
    __shared__ __align__(16) float swb[128];
    __shared__ __align__(8)  float2 smeta[8][32];   // (ee, src-as-float-bits)
    __shared__ __align__(16) float4 sH[8][4][32];   // 4 staged hn per warp
    int tid = threadIdx.x;
    if (tid < 128) { sb1[tid] = b1[tid]; sW2[tid] = W2[tid]; swb[tid] = W_nm[128 * 128 + tid]; }
    __syncthreads();
    float b2v = b2[0];

    int warp = tid >> 5, lane = tid & 31;
    int l4 = 4 * lane;
    const unsigned FULL = 0xffffffffu;

    for (int base = blockIdx.x * 32; base < NN; base += gridDim.x * 32) {
        int v0 = base + warp * 4;

        // phase 1: gather 4 nodes -> sH
#pragma unroll 1
        for (int j = 0; j < 4; ++j) {
            int v = v0 + j;
            float4 hn = make_float4(0.f, 0.f, 0.f, 0.f);
            if (v < NN) {
                int s0 = g_off[v], s1 = g_off[v + 1];
                if (s0 < s1) {
                    unsigned long long acc0 = 0ull, acc1 = 0ull;
                    float se = 0.f, st = 0.f;
                    for (int cb = s0; cb < s1; cb += 32) {
                        int n = min(32, s1 - cb);
                        if (lane < n) {
                            int4 md = __ldg(&g_elb[cb + lane]);
                            float ee = __int_as_float(md.y);
                            se += ee;
                            st += __int_as_float(md.z);
                            smeta[warp][lane] = make_float2(ee, __int_as_float(md.x));
                        }
                        __syncwarp();
#pragma unroll 4
                        for (int jj = 0; jj < n; ++jj) {
                            float2 m = smeta[warp][jj];
                            float ee = m.x;
                            int   sv = __float_as_int(m.y);
                            uint2 raw = __ldg((const uint2*)&g_Ah[(size_t)sv * 64 + 2 * lane]);
                            float2 f0 = __half22float2(*(__half2*)&raw.x);
                            float2 f1 = __half22float2(*(__half2*)&raw.y);
                            unsigned long long ev = pk2(ee, ee);
                            acc0 = fma2(ev, pk2(f0.x, f0.y), acc0);
                            acc1 = fma2(ev, pk2(f1.x, f1.y), acc1);
                        }
                        __syncwarp();
                    }
#pragma unroll
                    for (int o = 16; o > 0; o >>= 1) {
                        se += __shfl_xor_sync(FULL, se, o);
                        st += __shfl_xor_sync(FULL, st, o);
                    }
                    float inv = 1.f / se;
                    float tb = st * inv;
                    float2 a01 = upk2(acc0), a23 = upk2(acc1);
                    float4 B4 = __ldg((const float4*)&g_B[(size_t)v * 128 + l4]);
                    float4 wb = *(const float4*)&swb[l4];
                    hn.x = fmaxf(fmaf(a01.x, inv, B4.x) + wb.x * tb, 0.f);
                    hn.y = fmaxf(fmaf(a01.y, inv, B4.y) + wb.y * tb, 0.f);
                    hn.z = fmaxf(fmaf(a23.x, inv, B4.z) + wb.z * tb, 0.f);
                    hn.w = fmaxf(fmaf(a23.y, inv, B4.w) + wb.w * tb, 0.f);
                }
            }
            sH[warp][j][lane] = hn;
        }
        __syncwarp();

        // phase 2: joint out-MLP for 4 nodes (shared W1 loads + shared skip)
        unsigned long long a0[4], a1[4];
#pragma unroll
        for (int j = 0; j < 4; ++j) {
            a0[j] = pk2(sb1[l4], sb1[l4 + 1]);
            a1[j] = pk2(sb1[l4 + 2], sb1[l4 + 3]);
        }
#pragma unroll 2
        for (int kg = 0; kg < 32; ++kg) {
            float4 h0 = sH[warp][0][kg];
            float4 h1 = sH[warp][1][kg];
            float4 h2 = sH[warp][2][kg];
            float4 h3 = sH[warp][3][kg];
#pragma unroll
            for (int c = 0; c < 4; ++c) {
                float x0 = (c == 0) ? h0.x : (c == 1) ? h0.y : (c == 2) ? h0.z : h0.w;
                float x1 = (c == 0) ? h1.x : (c == 1) ? h1.y : (c == 2) ? h1.z : h1.w;
                float x2 = (c == 0) ? h2.x : (c == 1) ? h2.y : (c == 2) ? h2.z : h2.w;
                float x3 = (c == 0) ? h3.x : (c == 1) ? h3.y : (c == 2) ? h3.z : h3.w;
                if (fabsf(x0) + fabsf(x1) + fabsf(x2) + fabsf(x3) != 0.f) {  // warp-uniform
                    ulonglong2 w = __ldg((const ulonglong2*)&W1[(kg * 4 + c) * 128 + l4]);
                    unsigned long long p0 = pk2(x0, x0);
                    unsigned long long p1 = pk2(x1, x1);
                    unsigned long long p2 = pk2(x2, x2);
                    unsigned long long p3 = pk2(x3, x3);
                    a0[0] = fma2(p0, w.x, a0[0]); a1[0] = fma2(p0, w.y, a1[0]);
                    a0[1] = fma2(p1, w.x, a0[1]); a1[1] = fma2(p1, w.y, a1[1]);
                    a0[2] = fma2(p2, w.x, a0[2]); a1[2] = fma2(p2, w.y, a1[2]);
                    a0[3] = fma2(p3, w.x, a0[3]); a1[3] = fma2(p3, w.y, a1[3]);
                }
            }
        }
        // epilogue per node
        float4 w2 = *(const float4*)&sW2[l4];
#pragma unroll
        for (int j = 0; j < 4; ++j) {
            float2 q01 = upk2(a0[j]), q23 = upk2(a1[j]);
            float p = lrelu(q01.x, 0.1f) * w2.x + lrelu(q01.y, 0.1f) * w2.y +
                      lrelu(q23.x, 0.1f) * w2.z + lrelu(q23.y, 0.1f) * w2.w;
#pragma unroll
            for (int o = 16; o > 0; o >>= 1) p += __shfl_xor_sync(FULL, p, o);
            int v = v0 + j;
            if (lane == 0 && v < NN) {
                out[v] = p + b2v;
                g_deg[v] = 0;          // restore zero invariant for next run
            }
        }
    }
}

// ---------------- launch -----------------------------------------------------
extern "C" void kernel_launch(void* const* d_in, const int* in_sizes, int n_in,
                              void* d_out, int out_size) {
    const float* feat    = (const float*)d_in[0];
    const float* bit     = (const float*)d_in[1];
    const int*   src     = (const int*)d_in[2];
    const int*   dst     = (const int*)d_in[3];
    const float* W_self1 = (const float*)d_in[4];
    const float* b_self1 = (const float*)d_in[5];
    const float* W_self2 = (const float*)d_in[6];
    const float* b_self2 = (const float*)d_in[7];
    const float* W_nm    = (const float*)d_in[8];
    const float* b_nm    = (const float*)d_in[9];
    const float* attn    = (const float*)d_in[10];
    const float* W_out1  = (const float*)d_in[11];
    const float* b_out1  = (const float*)d_in[12];
    const float* W_out2  = (const float*)d_in[13];
    const float* b_out2  = (const float*)d_in[14];
    float* out = (float*)d_out;

    f0w<<<33, 256>>>(W_self2, b_self2, W_nm, attn);
    k1h<<<NB1, 256>>>(feat, dst, W_self1, b_self1, W_nm, b_nm, attn);
    kscan<<<NSB, 512>>>();
    k2_scatter<<<(EE + 255) / 256, 256>>>(src, dst, bit);
    k3_fused<<<NB1, 256>>>(W_nm, W_out1, b_out1, W_out2, b_out2, out);
}

// round 17
// speedup vs baseline: 1.2810x; 1.0660x over previous
#include <cuda_runtime.h>
#include <cuda_fp16.h>
#include <math.h>

#define NN 100000
#define NP 106496         // NN padded to 8192 multiple (scan tiles)
#define EE 1600000
#define FF 16
#define HH 128
#define NSB 13            // scan blocks: NP/8192
#define NB1 592           // k1 persistent blocks
#define NEB 2703          // hist edges per k1 block (592*2703 >= EE)

// ---------------- scratch (device globals; zero-init at module load) -------
__device__ __align__(16) __half2 g_Ah[(size_t)NN * 64];  // h @ W_h (fp16, 256B/row)
__device__ __align__(16) float g_B[(size_t)NN * HH];     // feat @ W_f + b_nm
__device__ float g_as[NN];
__device__ float g_ad[NN];
__device__ __align__(16) int g_deg[NP];   // ZERO invariant: reset by k3 each run
__device__ __align__(16) int g_off[NP];
__device__ __align__(16) int g_cur[NP];
__device__ volatile int g_sstat[NSB];     // ZERO invariant: reset by scatter
__device__ volatile int g_sagg[NSB];
__device__ volatile int g_spref[NSB];
__device__ __align__(16) int4 g_elb[EE];  // CSR-ordered (src, ee, ee*bit, pad)
__device__ __align__(16) float g_W2h[64 * HH];
__device__ __align__(16) float g_bA[HH];
__device__ float g_c;

__device__ __forceinline__ float lrelu(float x, float s) { return fmaxf(x, s * x); }

// packed fp32x2 helpers (Blackwell FFMA2: 2x fp32 FMA per issue slot)
__device__ __forceinline__ unsigned long long pk2(float x, float y) {
    unsigned long long r; asm("mov.b64 %0,{%1,%2};" : "=l"(r) : "f"(x), "f"(y)); return r;
}
__device__ __forceinline__ float2 upk2(unsigned long long v) {
    float2 r; asm("mov.b64 {%0,%1},%2;" : "=f"(r.x), "=f"(r.y) : "l"(v)); return r;
}
__device__ __forceinline__ unsigned long long fma2(unsigned long long a,
                                                   unsigned long long b,
                                                   unsigned long long c) {
    unsigned long long d;
    asm("fma.rn.f32x2 %0,%1,%2,%3;" : "=l"(d) : "l"(a), "l"(b), "l"(c));
    return d;
}

// ---------------- f0w: W2h fold + bias + c (weights only, 33 blocks) -------
__global__ __launch_bounds__(256) void f0w(
    const float* __restrict__ W_self2, const float* __restrict__ b_self2,
    const float* __restrict__ W_nm, const float* __restrict__ attn) {
    int bid = blockIdx.x, tid = threadIdx.x;
    if (bid < 32) {                        // 2 rows of W2h per block
        int i = bid * 2 + (tid >> 7);
        int j = tid & 127;
        float acc = 0.f;
        for (int k = 0; k < 128; ++k)
            acc = fmaf(W_self2[i * 128 + k], W_nm[k * 128 + j], acc);
        g_W2h[i * 128 + j] = acc;
    } else {                               // bias fold + scalar c
        __shared__ float red[128];
        if (tid < 128) {
            float acc = 0.f;
            for (int k = 0; k < 128; ++k)
                acc = fmaf(b_self2[k], W_nm[k * 128 + tid], acc);
            g_bA[tid] = acc;
            red[tid] = W_nm[128 * 128 + tid] * attn[tid];  // w_b row . attn
        }
        __syncthreads();
        for (int s = 64; s > 0; s >>= 1) {
            if (tid < s) red[tid] += red[tid + s];
            __syncthreads();
        }
        if (tid == 0) g_c = red[0];
    }
}

// ---------------- k1h: hist slice + per-node A(fp16), B, a_s, a_d ----------
#define NPW 4
__global__ __launch_bounds__(256) void k1h(
    const float* __restrict__ feat, const int* __restrict__ dst,
    const float* __restrict__ W1, const float* __restrict__ b1,
    const float* __restrict__ W_nm, const float* __restrict__ b_nm,
    const float* __restrict__ attn) {
    __shared__ __align__(16) float sW1[16 * 64];
    __shared__ __align__(16) float sW2h[64 * 128];
    __shared__ __align__(16) float sWf[16 * 128];
    __shared__ __align__(16) float sb1[64];
    __shared__ __align__(16) float sbnm[128];
    __shared__ __align__(16) float sbA[128];
    __shared__ __align__(16) float sattn[128];
    int tid = threadIdx.x;

    // histogram slice (g_deg is zero on entry: module init / k3 reset)
    {
        int e0 = blockIdx.x * NEB;
        int e1 = min(EE, e0 + NEB);
        for (int e = e0 + tid; e < e1; e += 256)
            atomicAdd(&g_deg[dst[e]], 1);
    }

    for (int i = tid; i < 16 * 64; i += 256) sW1[i] = W1[i];
    for (int i = tid; i < 64 * 128; i += 256) sW2h[i] = g_W2h[i];
    for (int i = tid; i < 16 * 128; i += 256) sWf[i] = W_nm[129 * 128 + i];
    if (tid < 64) sb1[tid] = b1[tid];
    if (tid < 128) { sbnm[tid] = b_nm[tid]; sbA[tid] = g_bA[tid]; sattn[tid] = attn[tid]; }
    __syncthreads();

    int warp = tid >> 5, lane = tid & 31;
    const unsigned FULL = 0xffffffffu;
    int l4 = 4 * lane;
    const int STRIDE = 8 * NPW;

    for (int base = blockIdx.x * STRIDE; base < NN; base += gridDim.x * STRIDE) {
        int v0 = base + warp * NPW;
        if (v0 >= NN) continue;
        bool full = (v0 + NPW <= NN);

        float f[NPW];
#pragma unroll
        for (int i = 0; i < NPW; ++i) {
            int v = v0 + i;
            f[i] = (lane < 16 && (full || v < NN)) ? feat[(size_t)v * 16 + lane] : 0.f;
        }

        float u0[NPW], u1[NPW];
#pragma unroll
        for (int i = 0; i < NPW; ++i) { u0[i] = sb1[lane]; u1[i] = sb1[lane + 32]; }
#pragma unroll
        for (int k = 0; k < 16; ++k) {
            float w0 = sW1[k * 64 + lane];
            float w1 = sW1[k * 64 + lane + 32];
#pragma unroll
            for (int i = 0; i < NPW; ++i) {
                float fk = __shfl_sync(FULL, f[i], k);
                u0[i] = fmaf(fk, w0, u0[i]);
                u1[i] = fmaf(fk, w1, u1[i]);
            }
        }
#pragma unroll
        for (int i = 0; i < NPW; ++i) {
            u0[i] = lrelu(u0[i], 0.1f);
            u1[i] = lrelu(u1[i], 0.1f);
        }

        unsigned long long a0[NPW], a1[NPW];
#pragma unroll
        for (int i = 0; i < NPW; ++i) {
            a0[i] = pk2(sbA[l4], sbA[l4 + 1]);
            a1[i] = pk2(sbA[l4 + 2], sbA[l4 + 3]);
        }
#pragma unroll 8
        for (int k = 0; k < 64; ++k) {
            ulonglong2 w = *(const ulonglong2*)&sW2h[k * 128 + l4];
#pragma unroll
            for (int i = 0; i < NPW; ++i) {
                float uk = (k < 32) ? __shfl_sync(FULL, u0[i], k)
                                    : __shfl_sync(FULL, u1[i], k - 32);
                unsigned long long uu = pk2(uk, uk);
                a0[i] = fma2(uu, w.x, a0[i]);
                a1[i] = fma2(uu, w.y, a1[i]);
            }
        }
        float4 at = *(const float4*)&sattn[l4];
        float av4[NPW];
#pragma unroll
        for (int i = 0; i < NPW; ++i) {
            int v = v0 + i;
            if (!full && v >= NN) { av4[i] = 0.f; continue; }
            float2 x01 = upk2(a0[i]), x23 = upk2(a1[i]);
            __half2 h0 = __floats2half2_rn(x01.x, x01.y);
            __half2 h1 = __floats2half2_rn(x23.x, x23.y);
            uint2 hp;
            hp.x = *(unsigned*)&h0;
            hp.y = *(unsigned*)&h1;
            *(uint2*)&g_Ah[(size_t)v * 64 + 2 * lane] = hp;
            av4[i] = x01.x * at.x + x01.y * at.y + x23.x * at.z + x23.y * at.w;
        }

        unsigned long long c0[NPW], c1[NPW];
#pragma unroll
        for (int i = 0; i < NPW; ++i) {
            c0[i] = pk2(sbnm[l4], sbnm[l4 + 1]);
            c1[i] = pk2(sbnm[l4 + 2], sbnm[l4 + 3]);
        }
#pragma unroll
        for (int k = 0; k < 16; ++k) {
            ulonglong2 w = *(const ulonglong2*)&sWf[k * 128 + l4];
#pragma unroll
            for (int i = 0; i < NPW; ++i) {
                float fk = __shfl_sync(FULL, f[i], k);
                unsigned long long ff = pk2(fk, fk);
                c0[i] = fma2(ff, w.x, c0[i]);
                c1[i] = fma2(ff, w.y, c1[i]);
            }
        }
#pragma unroll
        for (int i = 0; i < NPW; ++i) {
            int v = v0 + i;
            if (!full && v >= NN) continue;
            float2 b01 = upk2(c0[i]), b23 = upk2(c1[i]);
            float4 b = make_float4(b01.x, b01.y, b23.x, b23.y);
            *(float4*)&g_B[(size_t)v * 128 + l4] = b;
            float ps = av4[i];
            float pd = b.x * at.x + b.y * at.y + b.z * at.z + b.w * at.w;
#pragma unroll
            for (int s = 16; s > 0; s >>= 1) {
                ps += __shfl_xor_sync(FULL, ps, s);
                pd += __shfl_xor_sync(FULL, pd, s);
            }
            if (lane == 0) { g_as[v] = ps; g_ad[v] = pd; }
        }
    }
}

// ---------------- kscan: decoupled-lookback scan, 16 elems/thread -----------
__global__ __launch_bounds__(512) void kscan() {
    __shared__ int s[512];
    __shared__ int sh_run;
    int b = blockIdx.x, tid = threadIdx.x;
    int base = b * 8192 + tid * 16;
    int4 d[4];
    int ps[4];
    int tsum = 0;
#pragma unroll
    for (int q = 0; q < 4; ++q) {
        d[q] = *(const int4*)&g_deg[base + q * 4];
        ps[q] = tsum;                       // prefix before this quad
        tsum += d[q].x + d[q].y + d[q].z + d[q].w;
    }
    s[tid] = tsum;
    __syncthreads();
    for (int o = 1; o < 512; o <<= 1) {
        int t = (tid >= o) ? s[tid - o] : 0;
        __syncthreads();
        s[tid] += t;
        __syncthreads();
    }
    int incl = s[tid];
    int total = s[511];
    if (tid == 0) {
        g_sagg[b] = total;
        __threadfence();
        if (b == 0) {
            g_spref[0] = total;
            __threadfence();
            g_sstat[0] = 2;
            sh_run = 0;
        } else {
            g_sstat[b] = 1;
            int running = 0;
            int j = b - 1;
            while (true) {
                int st;
                while ((st = g_sstat[j]) == 0) { }
                if (st == 2) { running += g_spref[j]; break; }
                running += g_sagg[j];
                --j;
            }
            g_spref[b] = running + total;
            __threadfence();
            g_sstat[b] = 2;
            sh_run = running;
        }
    }
    __syncthreads();
    int e = incl - tsum + sh_run;
#pragma unroll
    for (int q = 0; q < 4; ++q) {
        int e0 = e + ps[q];
        int e1 = e0 + d[q].x, e2 = e1 + d[q].y, e3 = e2 + d[q].z;
        int4 ev = make_int4(e0, e1, e2, e3);
        *(int4*)&g_off[base + q * 4] = ev;
        *(int4*)&g_cur[base + q * 4] = ev;
    }
}

// scatter + edge logit + exp; 16B record/edge; resets scan statuses for next run
__global__ void k2_scatter(const int* __restrict__ src,
                           const int* __restrict__ dst,
                           const float* __restrict__ bit) {
    if (blockIdx.x == 0 && threadIdx.x < NSB) g_sstat[threadIdx.x] = 0;
    int i = blockIdx.x * blockDim.x + threadIdx.x;
    if (i < EE) {
        int s = src[i], d = dst[i];
        float bv = bit[i];
        float lg = g_as[s] + g_ad[d] + g_c * bv;
        lg = fmaxf(lg, 0.2f * lg);
        float ee = __expf(lg);
        int pos = atomicAdd(&g_cur[d], 1);
        g_elb[pos] = make_int4(s, __float_as_int(ee), __float_as_int(ee * bv), 0);
    }
}

// ---------------- k3: softmax-agg + out MLP fused (4 nodes per warp) -------
// Non-persistent: 3125 blocks x 32 nodes = NN exactly (HW wave balancing,
// zero bounds checks). Gather 8 LDGs in flight; out-MLP 4-node blocked.
__global__ __launch_bounds__(256, 4) void k3_fused(
    const float* __restrict__ W_nm,
    const float* __restrict__ W1, const float* __restrict__ b1,
    const float* __restrict__ W2, const float* __restrict__ b2,
    float* __restrict__ out) {
    __shared__ __align__(16) float sb1[128];
    __shared__ __align__(16) float sW2[128];
    __shared__ __align__(16) float swb[128];
    __shared__ __align__(8)  float2 smeta[8][32];   // (ee, src-as-float-bits)
    __shared__ __align__(16) float4 sH[8][4][32];   // 4 staged hn per warp
    int tid = threadIdx.x;
    if (tid < 128) { sb1[tid] = b1[tid]; sW2[tid] = W2[tid]; swb[tid] = W_nm[128 * 128 + tid]; }
    __syncthreads();
    float b2v = b2[0];

    int warp = tid >> 5, lane = tid & 31;
    int l4 = 4 * lane;
    const unsigned FULL = 0xffffffffu;
    int v0 = blockIdx.x * 32 + warp * 4;   // exact fit, no guards

    // phase 1: gather 4 nodes -> sH
#pragma unroll 1
    for (int j = 0; j < 4; ++j) {
        int v = v0 + j;
        float4 hn = make_float4(0.f, 0.f, 0.f, 0.f);
        int s0 = g_off[v], s1 = g_off[v + 1];
        if (s0 < s1) {
            unsigned long long acc0 = 0ull, acc1 = 0ull;
            float se = 0.f, st = 0.f;
            for (int cb = s0; cb < s1; cb += 32) {
                int n = min(32, s1 - cb);
                if (lane < n) {
                    int4 md = __ldg(&g_elb[cb + lane]);
                    float ee = __int_as_float(md.y);
                    se += ee;
                    st += __int_as_float(md.z);
                    smeta[warp][lane] = make_float2(ee, __int_as_float(md.x));
                }
                __syncwarp();
#pragma unroll 8
                for (int jj = 0; jj < n; ++jj) {
                    float2 m = smeta[warp][jj];
                    float ee = m.x;
                    int   sv = __float_as_int(m.y);
                    uint2 raw = __ldg((const uint2*)&g_Ah[(size_t)sv * 64 + 2 * lane]);
                    float2 f0 = __half22float2(*(__half2*)&raw.x);
                    float2 f1 = __half22float2(*(__half2*)&raw.y);
                    unsigned long long ev = pk2(ee, ee);
                    acc0 = fma2(ev, pk2(f0.x, f0.y), acc0);
                    acc1 = fma2(ev, pk2(f1.x, f1.y), acc1);
                }
                __syncwarp();
            }
#pragma unroll
            for (int o = 16; o > 0; o >>= 1) {
                se += __shfl_xor_sync(FULL, se, o);
                st += __shfl_xor_sync(FULL, st, o);
            }
            float inv = 1.f / se;
            float tb = st * inv;
            float2 a01 = upk2(acc0), a23 = upk2(acc1);
            float4 B4 = __ldg((const float4*)&g_B[(size_t)v * 128 + l4]);
            float4 wb = *(const float4*)&swb[l4];
            hn.x = fmaxf(fmaf(a01.x, inv, B4.x) + wb.x * tb, 0.f);
            hn.y = fmaxf(fmaf(a01.y, inv, B4.y) + wb.y * tb, 0.f);
            hn.z = fmaxf(fmaf(a23.x, inv, B4.z) + wb.z * tb, 0.f);
            hn.w = fmaxf(fmaf(a23.y, inv, B4.w) + wb.w * tb, 0.f);
        }
        sH[warp][j][lane] = hn;
    }
    __syncwarp();

    // phase 2: joint out-MLP for 4 nodes (shared W1 loads + shared skip)
    unsigned long long a0[4], a1[4];
#pragma unroll
    for (int j = 0; j < 4; ++j) {
        a0[j] = pk2(sb1[l4], sb1[l4 + 1]);
        a1[j] = pk2(sb1[l4 + 2], sb1[l4 + 3]);
    }
#pragma unroll 2
    for (int kg = 0; kg < 32; ++kg) {
        float4 h0 = sH[warp][0][kg];
        float4 h1 = sH[warp][1][kg];
        float4 h2 = sH[warp][2][kg];
        float4 h3 = sH[warp][3][kg];
#pragma unroll
        for (int c = 0; c < 4; ++c) {
            float x0 = (c == 0) ? h0.x : (c == 1) ? h0.y : (c == 2) ? h0.z : h0.w;
            float x1 = (c == 0) ? h1.x : (c == 1) ? h1.y : (c == 2) ? h1.z : h1.w;
            float x2 = (c == 0) ? h2.x : (c == 1) ? h2.y : (c == 2) ? h2.z : h2.w;
            float x3 = (c == 0) ? h3.x : (c == 1) ? h3.y : (c == 2) ? h3.z : h3.w;
            if (fabsf(x0) + fabsf(x1) + fabsf(x2) + fabsf(x3) != 0.f) {  // warp-uniform
                ulonglong2 w = __ldg((const ulonglong2*)&W1[(kg * 4 + c) * 128 + l4]);
                unsigned long long p0 = pk2(x0, x0);
                unsigned long long p1 = pk2(x1, x1);
                unsigned long long p2 = pk2(x2, x2);
                unsigned long long p3 = pk2(x3, x3);
                a0[0] = fma2(p0, w.x, a0[0]); a1[0] = fma2(p0, w.y, a1[0]);
                a0[1] = fma2(p1, w.x, a0[1]); a1[1] = fma2(p1, w.y, a1[1]);
                a0[2] = fma2(p2, w.x, a0[2]); a1[2] = fma2(p2, w.y, a1[2]);
                a0[3] = fma2(p3, w.x, a0[3]); a1[3] = fma2(p3, w.y, a1[3]);
            }
        }
    }
    // epilogue per node
    float4 w2 = *(const float4*)&sW2[l4];
#pragma unroll
    for (int j = 0; j < 4; ++j) {
        float2 q01 = upk2(a0[j]), q23 = upk2(a1[j]);
        float p = lrelu(q01.x, 0.1f) * w2.x + lrelu(q01.y, 0.1f) * w2.y +
                  lrelu(q23.x, 0.1f) * w2.z + lrelu(q23.y, 0.1f) * w2.w;
#pragma unroll
        for (int o = 16; o > 0; o >>= 1) p += __shfl_xor_sync(FULL, p, o);
        if (lane == 0) {
            int v = v0 + j;
            out[v] = p + b2v;
            g_deg[v] = 0;              // restore zero invariant for next run
        }
    }
}

// ---------------- launch -----------------------------------------------------
extern "C" void kernel_launch(void* const* d_in, const int* in_sizes, int n_in,
                              void* d_out, int out_size) {
    const float* feat    = (const float*)d_in[0];
    const float* bit     = (const float*)d_in[1];
    const int*   src     = (const int*)d_in[2];
    const int*   dst     = (const int*)d_in[3];
    const float* W_self1 = (const float*)d_in[4];
    const float* b_self1 = (const float*)d_in[5];
    const float* W_self2 = (const float*)d_in[6];
    const float* b_self2 = (const float*)d_in[7];
    const float* W_nm    = (const float*)d_in[8];
    const float* b_nm    = (const float*)d_in[9];
    const float* attn    = (const float*)d_in[10];
    const float* W_out1  = (const float*)d_in[11];
    const float* b_out1  = (const float*)d_in[12];
    const float* W_out2  = (const float*)d_in[13];
    const float* b_out2  = (const float*)d_in[14];
    float* out = (float*)d_out;

    f0w<<<33, 256>>>(W_self2, b_self2, W_nm, attn);
    k1h<<<NB1, 256>>>(feat, dst, W_self1, b_self1, W_nm, b_nm, attn);
    kscan<<<NSB, 512>>>();
    k2_scatter<<<(EE + 255) / 256, 256>>>(src, dst, bit);
    k3_fused<<<3125, 256>>>(W_nm, W_out1, b_out1, W_out2, b_out2, out);
}